// round 12
// baseline (speedup 1.0000x reference)
#include <cuda_runtime.h>
#include <cuda_fp16.h>
#include <math.h>

#define NN   100000
#define NNP  100032             // padded to 64*1563
#define MM   12
#define ORIGF 92
#define NBRF 41
#define AA   64
#define A2   128
#define HH   128
#define NCONVL 3
#define NC0  1000
#define EPSL 1e-5f
#define NE   (NN * MM)          // 1.2M edges
#define KP   48                 // padded K for edge GEMM

typedef unsigned long long ull;

// ---------------- scratch ----------------
__device__ float   g_x[NN * AA];
__device__ __half  g_xh[NNP * AA];                  // fp16 mirror of x (padding stays 0)
__device__ __half  g_ch[NNP * A2];                  // c fp16
__device__ __half  g_dh[NNP * A2];                  // d fp16
__device__ __half  g_nfe[(size_t)NE * KP];          // edge features fp16, [e][48] zero-padded
__device__ uint2   g_w3f[NCONVL][3 * 16 * 32];      // W3 B-fragments per layer (K=48)
__device__ uint2   g_wcdf[NCONVL][2 * 4 * 16 * 32]; // Wc/Wd B-fragments per layer (K=64)
__device__ float   g_ns[NN * AA];
__device__ double  g_s1[A2], g_q1[A2];
__device__ double  g_s2[AA], g_q2[AA];
__device__ float   g_scale1[A2], g_shift1[A2];
__device__ float   g_scale2[AA], g_shift2[AA];

// ---------------- f32x2 helpers (embed GEMM) ----------------
__device__ __forceinline__ ull pack2(float lo, float hi) {
    ull r; asm("mov.b64 %0, {%1, %2};" : "=l"(r) : "f"(lo), "f"(hi)); return r;
}
__device__ __forceinline__ ull dup2(float v) { return pack2(v, v); }
__device__ __forceinline__ void fma2(ull& d, ull a, ull b) {
    asm("fma.rn.f32x2 %0, %1, %2, %0;" : "+l"(d) : "l"(a), "l"(b));
}
__device__ __forceinline__ float2 unpack2(ull v) {
    float2 f; asm("mov.b64 {%0, %1}, %2;" : "=f"(f.x), "=f"(f.y) : "l"(v)); return f;
}

__device__ __forceinline__ unsigned h2_to_u(__half2 h) { return *(unsigned*)&h; }
__device__ __forceinline__ float2 u_to_f2(unsigned u) { return __half22float2(*(__half2*)&u); }

// ---------------- activations ----------------
__device__ __forceinline__ float sp_f(float x) {
    return fmaxf(x, 0.f) + __logf(1.f + __expf(-fabsf(x)));
}
__device__ __forceinline__ float sg_f(float x) {
    return __fdividef(1.f, 1.f + __expf(-x));
}

// ---------------- HMMA m16n8k16 row.col f16f16 -> f32 ----------------
__device__ __forceinline__ void mma16816(float& c0, float& c1, float& c2, float& c3,
                                         unsigned a0, unsigned a1, unsigned a2, unsigned a3,
                                         unsigned b0, unsigned b1) {
    asm volatile(
        "mma.sync.aligned.m16n8k16.row.col.f32.f16.f16.f32 "
        "{%0,%1,%2,%3}, {%4,%5,%6,%7}, {%8,%9}, {%0,%1,%2,%3};\n"
        : "+f"(c0), "+f"(c1), "+f"(c2), "+f"(c3)
        : "r"(a0), "r"(a1), "r"(a2), "r"(a3), "r"(b0), "r"(b1));
}

// ================= prep: nbr_fea -> edge-major fp16, padded to 48 ==============
__global__ void nfe_prep(const float* __restrict__ nbr_fea) {
    const unsigned j = blockIdx.x * 256 + threadIdx.x;
    if (j >= (unsigned)NE * (KP / 2)) return;
    const unsigned e = j / (KP / 2);
    const int kk = (int)(j % (KP / 2)) * 2;
    const float v0 = (kk     < NBRF) ? nbr_fea[(size_t)e * NBRF + kk]     : 0.f;
    const float v1 = (kk + 1 < NBRF) ? nbr_fea[(size_t)e * NBRF + kk + 1] : 0.f;
    ((unsigned*)g_nfe)[j] = h2_to_u(__floats2half2_rn(v0, v1));
}

// ================= prep: W3 -> B-fragment layout (K pad 48) ====================
__global__ void w3f_prep(const float* __restrict__ conv_W) {
    const int idx = blockIdx.x * 256 + threadIdx.x;
    if (idx >= NCONVL * 3 * 16 * 32) return;
    const int lane  = idx & 31;
    const int nt    = (idx >> 5) & 15;
    const int ks    = (idx >> 9) % 3;
    const int layer = idx / (3 * 16 * 32);
    const float* W3 = conv_W + (size_t)layer * (2 * AA + NBRF) * A2 + 128 * A2;
    const int n  = nt * 8 + (lane >> 2);
    const int k0 = ks * 16 + (lane & 3) * 2;
    auto gw = [&](int k) -> float { return (k < NBRF) ? W3[k * A2 + n] : 0.f; };
    uint2 b;
    b.x = h2_to_u(__floats2half2_rn(gw(k0),     gw(k0 + 1)));
    b.y = h2_to_u(__floats2half2_rn(gw(k0 + 8), gw(k0 + 9)));
    g_w3f[layer][idx % (3 * 16 * 32)] = b;
}

// ================= prep: Wc/Wd -> B-fragment layout (K=64) =====================
__global__ void wcd_prep(const float* __restrict__ conv_W) {
    const int idx = blockIdx.x * 256 + threadIdx.x;
    if (idx >= NCONVL * 2 * 4 * 16 * 32) return;
    const int lane  = idx & 31;
    const int nt    = (idx >> 5) & 15;
    const int ks    = (idx >> 9) & 3;
    const int part  = (idx >> 11) & 1;
    const int layer = idx >> 12;
    const float* Wp = conv_W + (size_t)layer * (2 * AA + NBRF) * A2 + (size_t)part * 64 * A2;
    const int n  = nt * 8 + (lane >> 2);
    const int k0 = ks * 16 + (lane & 3) * 2;
    uint2 b;
    b.x = h2_to_u(__floats2half2_rn(Wp[k0 * A2 + n],       Wp[(k0 + 1) * A2 + n]));
    b.y = h2_to_u(__floats2half2_rn(Wp[(k0 + 8) * A2 + n], Wp[(k0 + 9) * A2 + n]));
    g_wcdf[layer][idx & 4095] = b;
}

// ================= embedding GEMM (once): x, xh = atom_fea @ emb_W + b =========
__global__ void __launch_bounds__(128)
embed_kernel(const float* __restrict__ in, const float* __restrict__ W,
             const float* __restrict__ bias, float* __restrict__ out,
             __half* __restrict__ outh, int nrows)
{
    __shared__ float saT[ORIGF * 64];
    __shared__ float sW[ORIGF * AA];
    const int t  = threadIdx.x;
    const int rg = t / 8;
    const int cg = t % 8;
    const int r0 = rg * 4;
    const int c0 = cg * 8;
    const int row0 = blockIdx.x * 64;

    for (int idx = t; idx < 64 * (ORIGF / 4); idx += 128) {
        const int r  = idx / (ORIGF / 4);
        const int kq = idx % (ORIGF / 4);
        float4 v = make_float4(0.f, 0.f, 0.f, 0.f);
        if (row0 + r < nrows) v = *(((const float4*)(in + (size_t)(row0 + r) * ORIGF)) + kq);
        saT[(4 * kq + 0) * 64 + r] = v.x;
        saT[(4 * kq + 1) * 64 + r] = v.y;
        saT[(4 * kq + 2) * 64 + r] = v.z;
        saT[(4 * kq + 3) * 64 + r] = v.w;
    }
    for (int idx = t; idx < ORIGF * AA / 4; idx += 128)
        ((float4*)sW)[idx] = ((const float4*)W)[idx];
    __syncthreads();

    ull acc[4][4];
#pragma unroll
    for (int r = 0; r < 4; r++)
#pragma unroll
        for (int cp = 0; cp < 4; cp++) acc[r][cp] = 0ULL;

#pragma unroll 4
    for (int k = 0; k < ORIGF; k++) {
        const float4 av = *((const float4*)(saT + k * 64 + r0));
        const ull A0 = dup2(av.x), A1 = dup2(av.y), A2r = dup2(av.z), A3 = dup2(av.w);
        const float* wr = sW + k * AA + c0;
        const ulonglong2 W03 = *((const ulonglong2*)wr);
        const ulonglong2 W47 = *((const ulonglong2*)(wr + 4));
        fma2(acc[0][0], A0, W03.x);  fma2(acc[0][1], A0, W03.y);
        fma2(acc[0][2], A0, W47.x);  fma2(acc[0][3], A0, W47.y);
        fma2(acc[1][0], A1, W03.x);  fma2(acc[1][1], A1, W03.y);
        fma2(acc[1][2], A1, W47.x);  fma2(acc[1][3], A1, W47.y);
        fma2(acc[2][0], A2r, W03.x); fma2(acc[2][1], A2r, W03.y);
        fma2(acc[2][2], A2r, W47.x); fma2(acc[2][3], A2r, W47.y);
        fma2(acc[3][0], A3, W03.x);  fma2(acc[3][1], A3, W03.y);
        fma2(acc[3][2], A3, W47.x);  fma2(acc[3][3], A3, W47.y);
    }

    float bb[8];
#pragma unroll
    for (int c = 0; c < 8; c++) bb[c] = bias[c0 + c];

#pragma unroll
    for (int r = 0; r < 4; r++) {
        const int rgl = row0 + r0 + r;
        if (rgl >= nrows) continue;
        float y[8];
#pragma unroll
        for (int cp = 0; cp < 4; cp++) {
            const float2 f = unpack2(acc[r][cp]);
            y[2 * cp]     = f.x + bb[2 * cp];
            y[2 * cp + 1] = f.y + bb[2 * cp + 1];
        }
        float4* op = (float4*)(out + (size_t)rgl * AA + c0);
        op[0] = make_float4(y[0], y[1], y[2], y[3]);
        op[1] = make_float4(y[4], y[5], y[6], y[7]);
        uint4 hh;
        unsigned* hv = (unsigned*)&hh;
#pragma unroll
        for (int cp = 0; cp < 4; cp++)
            hv[cp] = h2_to_u(__floats2half2_rn(y[2 * cp], y[2 * cp + 1]));
        *((uint4*)(outh + (size_t)rgl * AA + c0)) = hh;
    }
}

// ================= conv GEMM via HMMA: c,d = xh @ Wc, xh @ Wd ==================
// 128 threads (4 warps); block = 64 atoms; A fragments read from global xh.
__global__ void __launch_bounds__(128, 4)
convmma_kernel(const __half* __restrict__ xh, const uint2* __restrict__ wcdf,
               __half* __restrict__ outc, __half* __restrict__ outd)
{
    __shared__ __align__(16) uint2  sB[4 * 16 * 32];     // 16KB one W part
    __shared__ __align__(16) __half sy[64 * 136];        // 17KB output staging

    const int t    = threadIdx.x;
    const int w    = t >> 5;
    const int lane = t & 31;
    const int g    = lane >> 2;
    const int i    = lane & 3;
    const int row0 = blockIdx.x * 64;

    const unsigned* Ag = (const unsigned*)xh;
    const unsigned arow0 = (unsigned)(row0 + w * 16 + g) * 32;   // u32 pitch 32 (K=64 halves)
    const unsigned arow1 = arow0 + 8 * 32;

    for (int s = 0; s < 2; s++) {
        for (int idx = t; idx < 4 * 16 * 32; idx += 128) sB[idx] = wcdf[s * 2048 + idx];
        __syncthreads();

        float acc[16][4];
#pragma unroll
        for (int nt = 0; nt < 16; nt++)
#pragma unroll
            for (int c = 0; c < 4; c++) acc[nt][c] = 0.f;

#pragma unroll
        for (int ks = 0; ks < 4; ks++) {
            const unsigned a0 = Ag[arow0 + ks * 8 + i];
            const unsigned a1 = Ag[arow1 + ks * 8 + i];
            const unsigned a2 = Ag[arow0 + ks * 8 + i + 4];
            const unsigned a3 = Ag[arow1 + ks * 8 + i + 4];
#pragma unroll
            for (int nt = 0; nt < 16; nt++) {
                const uint2 b = sB[(ks * 16 + nt) * 32 + lane];
                mma16816(acc[nt][0], acc[nt][1], acc[nt][2], acc[nt][3],
                         a0, a1, a2, a3, b.x, b.y);
            }
        }

        const int r0 = w * 16 + g, r1 = r0 + 8;
#pragma unroll
        for (int nt = 0; nt < 16; nt++) {
            *((unsigned*)(sy + r0 * 136 + nt * 8 + i * 2)) =
                h2_to_u(__floats2half2_rn(acc[nt][0], acc[nt][1]));
            *((unsigned*)(sy + r1 * 136 + nt * 8 + i * 2)) =
                h2_to_u(__floats2half2_rn(acc[nt][2], acc[nt][3]));
        }
        __syncthreads();

        __half* outp = s ? outd : outc;
        for (int idx = t; idx < 64 * 16; idx += 128) {
            const int r = idx >> 4, ui = idx & 15;
            const uint4 vv = *((const uint4*)(sy + r * 136 + ui * 8));
            *((uint4*)(outp + (size_t)(row0 + r) * A2 + ui * 8)) = vv;
        }
        __syncthreads();
    }
}

// ---------------- zero BN stats (once at launch start) ----------------
__global__ void zero_stats_kernel() {
    const int t = threadIdx.x;
    if (t < A2) { g_s1[t] = 0.0; g_q1[t] = 0.0; }
    if (t < AA) { g_s2[t] = 0.0; g_q2[t] = 0.0; }
}

// ================= gated passes via HMMA, recompute (no y materialization) =====
// PHASE 0: compute y, accumulate BN1 stats.
// PHASE 1: recompute y, normalize, sigmoid*softplus, reduce over m -> ns + BN2 stats.
// Block = 192 edges = 16 atoms; 3 passes of 64 edges.
template <int PHASE>
__global__ void __launch_bounds__(128, 4)
gatedpass_kernel(const int* __restrict__ nbr_idx,
                 const uint2* __restrict__ w3f, const float* __restrict__ bias)
{
    __shared__ __align__(16) uint2  sB[3 * 16 * 32];     // 12KB B fragments
    __shared__ __align__(16) __half scd[64 * 136];       // 17KB cd / y buffer
    __shared__ float sns[2][16][64];                     // 8KB  ns accumulators (PHASE1)

    const int t    = threadIdx.x;
    const int w    = t >> 5;
    const int lane = t & 31;
    const int g    = lane >> 2;
    const int i    = lane & 3;

    for (int idx = t; idx < 3 * 16 * 32; idx += 128) sB[idx] = w3f[idx];
    const float4 bias4 = *((const float4*)(bias + lane * 4));

    float scf = 0.f, shf = 0.f, scc = 0.f, shc = 0.f;
    if (PHASE == 1) {
        for (int idx = t; idx < 2 * 16 * 64; idx += 128) ((float*)sns)[idx] = 0.f;
        const int a = t & 63;
        scf = g_scale1[a];      shf = g_shift1[a];
        scc = g_scale1[64 + a]; shc = g_shift1[64 + a];
    }

    float s_acc = 0.f, q_acc = 0.f;
    const unsigned eblock = blockIdx.x * 192;
    __syncthreads();

    for (int pass = 0; pass < 3; pass++) {
        const unsigned e0 = eblock + pass * 64;

        // ---- stage cd = c[n] + d[idx] + bias
        for (int k = 0; k < 16; k++) {
            const unsigned e = e0 + w * 16 + k;
            const unsigned n = e / MM;
            const int j = nbr_idx[e];
            const uint2 cu = ((const uint2*)g_ch)[(size_t)n * 32 + lane];
            const uint2 du = ((const uint2*)g_dh)[(size_t)j * 32 + lane];
            const float2 ca = u_to_f2(cu.x), cb2 = u_to_f2(cu.y);
            const float2 da = u_to_f2(du.x), db2 = u_to_f2(du.y);
            unsigned* dst = (unsigned*)(scd + (w * 16 + k) * 136 + lane * 4);
            dst[0] = h2_to_u(__floats2half2_rn(ca.x + da.x + bias4.x, ca.y + da.y + bias4.y));
            dst[1] = h2_to_u(__floats2half2_rn(cb2.x + db2.x + bias4.z, cb2.y + db2.y + bias4.w));
        }
        __syncthreads();

        // ---- mma: warp strip of 16 edges x 128 cols
        float acc[16][4];
#pragma unroll
        for (int nt = 0; nt < 16; nt++)
#pragma unroll
            for (int c = 0; c < 4; c++) acc[nt][c] = 0.f;

        const unsigned* Ag = (const unsigned*)g_nfe;
        const unsigned arow0 = (e0 + w * 16 + g) * (KP / 2);
        const unsigned arow1 = arow0 + 8 * (KP / 2);

#pragma unroll
        for (int ks = 0; ks < 3; ks++) {
            const unsigned a0 = Ag[arow0 + ks * 8 + i];
            const unsigned a1 = Ag[arow1 + ks * 8 + i];
            const unsigned a2 = Ag[arow0 + ks * 8 + i + 4];
            const unsigned a3 = Ag[arow1 + ks * 8 + i + 4];
#pragma unroll
            for (int nt = 0; nt < 16; nt++) {
                const uint2 b = sB[(ks * 16 + nt) * 32 + lane];
                mma16816(acc[nt][0], acc[nt][1], acc[nt][2], acc[nt][3],
                         a0, a1, a2, a3, b.x, b.y);
            }
        }

        // ---- y = acc + cd, write back into scd
        const int r0 = w * 16 + g, r1 = r0 + 8;
#pragma unroll
        for (int nt = 0; nt < 16; nt++) {
            unsigned* p0 = (unsigned*)(scd + r0 * 136 + nt * 8 + i * 2);
            unsigned* p1 = (unsigned*)(scd + r1 * 136 + nt * 8 + i * 2);
            const float2 cd0 = u_to_f2(*p0);
            const float2 cd1 = u_to_f2(*p1);
            *p0 = h2_to_u(__floats2half2_rn(acc[nt][0] + cd0.x, acc[nt][1] + cd0.y));
            *p1 = h2_to_u(__floats2half2_rn(acc[nt][2] + cd1.x, acc[nt][3] + cd1.y));
        }
        __syncthreads();

        if (PHASE == 0) {
            // BN1 stats: thread t sweeps column t
            for (int r = 0; r < 64; r++) {
                const float v = __half2float(scd[r * 136 + t]);
                s_acc += v; q_acc += v * v;
            }
        } else {
            // normalize + gate + reduce over m into sns
            const int half = t >> 6, a = t & 63;
            for (int rr = 0; rr < 32; rr++) {
                const int r = half * 32 + rr;
                const float yf = __half2float(scd[r * 136 + a]);
                const float yc = __half2float(scd[r * 136 + 64 + a]);
                const float gv = sg_f(yf * scf + shf) * sp_f(yc * scc + shc);
                const int at = (pass * 64 + r) / MM;
                sns[half][at][a] += gv;
            }
        }
        __syncthreads();
    }

    if (PHASE == 0) {
        atomicAdd(&g_s1[t], (double)s_acc);
        atomicAdd(&g_q1[t], (double)q_acc);
    } else {
        const int atom0 = blockIdx.x * 16;
        if (t < 64) {
            float s = 0.f, q = 0.f;
#pragma unroll
            for (int at = 0; at < 16; at++) {
                const float v = sns[0][at][t] + sns[1][at][t];
                g_ns[(size_t)(atom0 + at) * AA + t] = v;
                s += v; q += v * v;
            }
            atomicAdd(&g_s2[t], (double)s);
            atomicAdd(&g_q2[t], (double)q);
        }
    }
}

__global__ void finalize1_kernel(const float* __restrict__ g1, const float* __restrict__ b1) {
    const int o = threadIdx.x;
    const double cnt = (double)NN * MM;
    const double mean = g_s1[o] / cnt;
    const double var  = g_q1[o] / cnt - mean * mean;
    const float scale = g1[o] * rsqrtf((float)var + EPSL);
    g_scale1[o] = scale;
    g_shift1[o] = b1[o] - (float)mean * scale;
    g_s1[o] = 0.0; g_q1[o] = 0.0;      // ready for next layer / next replay
}

__global__ void finalize2_kernel(const float* __restrict__ g2, const float* __restrict__ b2) {
    const int a = threadIdx.x;
    const double cnt = (double)NN;
    const double mean = g_s2[a] / cnt;
    const double var  = g_q2[a] / cnt - mean * mean;
    const float scale = g2[a] * rsqrtf((float)var + EPSL);
    g_scale2[a] = scale;
    g_shift2[a] = b2[a] - (float)mean * scale;
    g_s2[a] = 0.0; g_q2[a] = 0.0;
}

// ---------------- update: x = softplus(x + ns*sc2 + sh2); also refresh xh ------
__global__ void update_kernel() {
    const int idx = blockIdx.x * blockDim.x + threadIdx.x;
    if (idx >= NN * (AA / 2)) return;
    const int a0 = (2 * idx) & 63;
    const float2 xv = *((const float2*)(g_x + (size_t)2 * idx));
    const float2 nv = *((const float2*)(g_ns + (size_t)2 * idx));
    const float v0 = sp_f(xv.x + nv.x * g_scale2[a0]     + g_shift2[a0]);
    const float v1 = sp_f(xv.y + nv.y * g_scale2[a0 + 1] + g_shift2[a0 + 1]);
    *((float2*)(g_x + (size_t)2 * idx)) = make_float2(v0, v1);
    ((unsigned*)g_xh)[idx] = h2_to_u(__floats2half2_rn(v0, v1));
}

// ---------------- fused pool + head ----------------
__global__ void head2_kernel(const float* __restrict__ fc_W, const float* __restrict__ fc_b,
                             const float* __restrict__ out_W, const float* __restrict__ out_b,
                             float* __restrict__ out)
{
    __shared__ float sred[2][64];
    __shared__ float spm[64];
    __shared__ float red[128];
    const int c = blockIdx.x, t = threadIdx.x;
    const int a = t & 63, half = t >> 6;

    float s = 0.f;
    const int r0 = c * 100 + half * 50;
    for (int i = 0; i < 50; i++) s += g_x[(r0 + i) * 64 + a];
    sred[half][a] = s;
    __syncthreads();
    if (t < 64) spm[t] = sp_f((sred[0][t] + sred[1][t]) * 0.01f);
    __syncthreads();

    float h = fc_b[t];
#pragma unroll
    for (int aa = 0; aa < 64; aa++) h += spm[aa] * fc_W[aa * HH + t];
    red[t] = sp_f(h) * out_W[t];
    __syncthreads();
    for (int sft = 64; sft > 0; sft >>= 1) {
        if (t < sft) red[t] += red[t + sft];
        __syncthreads();
    }
    if (t == 0) out[c] = red[0] + out_b[0];
}

// ---------------- host orchestration ----------------
extern "C" void kernel_launch(void* const* d_in, const int* in_sizes, int n_in,
                              void* d_out, int out_size)
{
    const float* atom_fea = (const float*)d_in[0];
    const float* nbr_fea  = (const float*)d_in[1];
    const int*   nbr_idx  = (const int*)  d_in[2];
    const float* emb_W    = (const float*)d_in[4];
    const float* emb_b    = (const float*)d_in[5];
    const float* conv_W   = (const float*)d_in[6];
    const float* conv_b   = (const float*)d_in[7];
    const float* bn1_g    = (const float*)d_in[8];
    const float* bn1_b    = (const float*)d_in[9];
    const float* bn2_g    = (const float*)d_in[10];
    const float* bn2_b    = (const float*)d_in[11];
    const float* fc_W     = (const float*)d_in[12];
    const float* fc_b     = (const float*)d_in[13];
    const float* out_W    = (const float*)d_in[14];
    const float* out_b    = (const float*)d_in[15];
    float* out = (float*)d_out;

    float *px;
    __half *pxh, *pc, *pd;
    uint2 *pw3f, *pwcdf;
    cudaGetSymbolAddress((void**)&px,    g_x);
    cudaGetSymbolAddress((void**)&pxh,   g_xh);
    cudaGetSymbolAddress((void**)&pc,    g_ch);
    cudaGetSymbolAddress((void**)&pd,    g_dh);
    cudaGetSymbolAddress((void**)&pw3f,  g_w3f);
    cudaGetSymbolAddress((void**)&pwcdf, g_wcdf);

    const int gemmBlocks = NNP / 64;   // 1563

    nfe_prep<<<(NE * (KP / 2) + 255) / 256, 256>>>(nbr_fea);
    w3f_prep<<<(NCONVL * 3 * 16 * 32 + 255) / 256, 256>>>(conv_W);
    wcd_prep<<<(NCONVL * 2 * 4 * 16 * 32 + 255) / 256, 256>>>(conv_W);
    embed_kernel<<<gemmBlocks, 128>>>(atom_fea, emb_W, emb_b, px, pxh, NN);
    zero_stats_kernel<<<1, 128>>>();

    for (int i = 0; i < NCONVL; i++) {
        if (i > 0) update_kernel<<<(NN * 32 + 255) / 256, 256>>>();
        convmma_kernel<<<gemmBlocks, 128>>>(pxh, pwcdf + (size_t)i * 4096, pc, pd);
        gatedpass_kernel<0><<<NE / 192, 128>>>(nbr_idx, pw3f + (size_t)i * 1536, conv_b + i * A2);
        finalize1_kernel<<<1, A2>>>(bn1_g + i * A2, bn1_b + i * A2);
        gatedpass_kernel<1><<<NE / 192, 128>>>(nbr_idx, pw3f + (size_t)i * 1536, conv_b + i * A2);
        finalize2_kernel<<<1, AA>>>(bn2_g + i * AA, bn2_b + i * AA);
    }

    update_kernel<<<(NN * 32 + 255) / 256, 256>>>();
    head2_kernel<<<NC0, 128>>>(fc_W, fc_b, out_W, out_b, out);
}

// round 14
// speedup vs baseline: 1.3081x; 1.3081x over previous
#include <cuda_runtime.h>
#include <cuda_fp16.h>
#include <math.h>

#define NN   100000
#define NNP  100032             // padded to 64*1563
#define MM   12
#define ORIGF 92
#define NBRF 41
#define AA   64
#define A2   128
#define HH   128
#define NCONVL 3
#define NC0  1000
#define EPSL 1e-5f
#define NE   (NN * MM)          // 1.2M edges
#define KP   48                 // padded K for edge GEMM

typedef unsigned long long ull;

// ---------------- scratch ----------------
__device__ float   g_x[NN * AA];
__device__ __half  g_xh[NNP * AA];                  // fp16 mirror of x (padding stays 0)
__device__ __half  g_ch[NNP * A2];                  // c fp16
__device__ __half  g_dh[NNP * A2];                  // d fp16
__device__ __half  g_nfe[(size_t)NE * KP];          // edge features fp16, [e][48] zero-padded
__device__ uint2   g_w3f[NCONVL][3 * 16 * 32];      // W3 B-fragments per layer (K=48)
__device__ uint2   g_wcdf[NCONVL][2 * 4 * 16 * 32]; // Wc/Wd B-fragments per layer (K=64)
__device__ __half  g_gatedh[(size_t)NE * A2];       // pre-BN gated, edge-major [e][128]
__device__ float   g_ns[NN * AA];
__device__ double  g_s1[A2], g_q1[A2];
__device__ double  g_s2[AA], g_q2[AA];
__device__ float   g_scale1[A2], g_shift1[A2];
__device__ float   g_scale2[AA], g_shift2[AA];

// ---------------- f32x2 helpers (embed GEMM) ----------------
__device__ __forceinline__ ull pack2(float lo, float hi) {
    ull r; asm("mov.b64 %0, {%1, %2};" : "=l"(r) : "f"(lo), "f"(hi)); return r;
}
__device__ __forceinline__ ull dup2(float v) { return pack2(v, v); }
__device__ __forceinline__ void fma2(ull& d, ull a, ull b) {
    asm("fma.rn.f32x2 %0, %1, %2, %0;" : "+l"(d) : "l"(a), "l"(b));
}
__device__ __forceinline__ float2 unpack2(ull v) {
    float2 f; asm("mov.b64 {%0, %1}, %2;" : "=f"(f.x), "=f"(f.y) : "l"(v)); return f;
}

__device__ __forceinline__ unsigned h2_to_u(__half2 h) { return *(unsigned*)&h; }
__device__ __forceinline__ float2 u_to_f2(unsigned u) { return __half22float2(*(__half2*)&u); }

// ---------------- activations ----------------
__device__ __forceinline__ float sp_f(float x) {
    return fmaxf(x, 0.f) + __logf(1.f + __expf(-fabsf(x)));
}
__device__ __forceinline__ float sg_f(float x) {
    return __fdividef(1.f, 1.f + __expf(-x));
}

// ---------------- HMMA m16n8k16 row.col f16f16 -> f32 ----------------
__device__ __forceinline__ void mma16816(float& c0, float& c1, float& c2, float& c3,
                                         unsigned a0, unsigned a1, unsigned a2, unsigned a3,
                                         unsigned b0, unsigned b1) {
    asm volatile(
        "mma.sync.aligned.m16n8k16.row.col.f32.f16.f16.f32 "
        "{%0,%1,%2,%3}, {%4,%5,%6,%7}, {%8,%9}, {%0,%1,%2,%3};\n"
        : "+f"(c0), "+f"(c1), "+f"(c2), "+f"(c3)
        : "r"(a0), "r"(a1), "r"(a2), "r"(a3), "r"(b0), "r"(b1));
}

// ================= prep: nbr_fea -> edge-major fp16, padded to 48 ==============
__global__ void nfe_prep(const float* __restrict__ nbr_fea) {
    const unsigned j = blockIdx.x * 256 + threadIdx.x;   // half2 slot
    if (j >= (unsigned)NE * (KP / 2)) return;
    const unsigned e = j / (KP / 2);
    const int kk = (int)(j % (KP / 2)) * 2;
    const float v0 = (kk     < NBRF) ? nbr_fea[(size_t)e * NBRF + kk]     : 0.f;
    const float v1 = (kk + 1 < NBRF) ? nbr_fea[(size_t)e * NBRF + kk + 1] : 0.f;
    ((unsigned*)g_nfe)[j] = h2_to_u(__floats2half2_rn(v0, v1));
}

// ================= prep: W3 -> B-fragment layout (K pad 48) ====================
__global__ void w3f_prep(const float* __restrict__ conv_W) {
    const int idx = blockIdx.x * 256 + threadIdx.x;      // over 3*3*16*32
    if (idx >= NCONVL * 3 * 16 * 32) return;
    const int lane  = idx & 31;
    const int nt    = (idx >> 5) & 15;
    const int ks    = (idx >> 9) % 3;
    const int layer = idx / (3 * 16 * 32);
    const float* W3 = conv_W + (size_t)layer * (2 * AA + NBRF) * A2 + 128 * A2;  // [41][128]
    const int n  = nt * 8 + (lane >> 2);
    const int k0 = ks * 16 + (lane & 3) * 2;
    auto gw = [&](int k) -> float { return (k < NBRF) ? W3[k * A2 + n] : 0.f; };
    uint2 b;
    b.x = h2_to_u(__floats2half2_rn(gw(k0),     gw(k0 + 1)));
    b.y = h2_to_u(__floats2half2_rn(gw(k0 + 8), gw(k0 + 9)));
    g_w3f[layer][idx % (3 * 16 * 32)] = b;
}

// ================= prep: Wc/Wd -> B-fragment layout (K=64) =====================
__global__ void wcd_prep(const float* __restrict__ conv_W) {
    const int idx = blockIdx.x * 256 + threadIdx.x;      // over 3*2*4*16*32
    if (idx >= NCONVL * 2 * 4 * 16 * 32) return;
    const int lane  = idx & 31;
    const int nt    = (idx >> 5) & 15;
    const int ks    = (idx >> 9) & 3;
    const int part  = (idx >> 11) & 1;
    const int layer = idx >> 12;
    const float* Wp = conv_W + (size_t)layer * (2 * AA + NBRF) * A2 + (size_t)part * 64 * A2;
    const int n  = nt * 8 + (lane >> 2);
    const int k0 = ks * 16 + (lane & 3) * 2;
    uint2 b;
    b.x = h2_to_u(__floats2half2_rn(Wp[k0 * A2 + n],       Wp[(k0 + 1) * A2 + n]));
    b.y = h2_to_u(__floats2half2_rn(Wp[(k0 + 8) * A2 + n], Wp[(k0 + 9) * A2 + n]));
    g_wcdf[layer][idx & 4095] = b;
}

// ================= embedding GEMM (once): g_x = atom_fea @ emb_W + b ===========
template <int K, int O>
__global__ void __launch_bounds__(256)
gemmT_kernel(const float* __restrict__ in, const float* __restrict__ W,
             const float* __restrict__ bias, float* __restrict__ out, int nrows)
{
    extern __shared__ char dsm[];
    float* saT = (float*)dsm;
    float* sW  = (float*)(dsm + (size_t)K * 64 * 4);

    const int nt = blockDim.x;
    const int t  = threadIdx.x;
    const int CG = O / 8;
    const int rg = t / CG;
    const int cg = t % CG;
    const int r0 = rg * 4;
    const int c0 = cg * 8;
    const int row0 = blockIdx.x * 64;

    for (int idx = t; idx < 64 * (K / 4); idx += nt) {
        const int r  = idx / (K / 4);
        const int kq = idx % (K / 4);
        float4 v = make_float4(0.f, 0.f, 0.f, 0.f);
        if (row0 + r < nrows) v = *(((const float4*)(in + (size_t)(row0 + r) * K)) + kq);
        saT[(4 * kq + 0) * 64 + r] = v.x;
        saT[(4 * kq + 1) * 64 + r] = v.y;
        saT[(4 * kq + 2) * 64 + r] = v.z;
        saT[(4 * kq + 3) * 64 + r] = v.w;
    }
    for (int idx = t; idx < K * O / 4; idx += nt)
        ((float4*)sW)[idx] = ((const float4*)W)[idx];
    __syncthreads();

    ull acc[4][4];
#pragma unroll
    for (int r = 0; r < 4; r++)
#pragma unroll
        for (int cp = 0; cp < 4; cp++) acc[r][cp] = 0ULL;

#pragma unroll 4
    for (int k = 0; k < K; k++) {
        const float4 av = *((const float4*)(saT + k * 64 + r0));
        const ull A0 = dup2(av.x), A1 = dup2(av.y), A2r = dup2(av.z), A3 = dup2(av.w);
        const float* wr = sW + k * O + c0;
        const ulonglong2 W03 = *((const ulonglong2*)wr);
        const ulonglong2 W47 = *((const ulonglong2*)(wr + 4));
        fma2(acc[0][0], A0, W03.x);  fma2(acc[0][1], A0, W03.y);
        fma2(acc[0][2], A0, W47.x);  fma2(acc[0][3], A0, W47.y);
        fma2(acc[1][0], A1, W03.x);  fma2(acc[1][1], A1, W03.y);
        fma2(acc[1][2], A1, W47.x);  fma2(acc[1][3], A1, W47.y);
        fma2(acc[2][0], A2r, W03.x); fma2(acc[2][1], A2r, W03.y);
        fma2(acc[2][2], A2r, W47.x); fma2(acc[2][3], A2r, W47.y);
        fma2(acc[3][0], A3, W03.x);  fma2(acc[3][1], A3, W03.y);
        fma2(acc[3][2], A3, W47.x);  fma2(acc[3][3], A3, W47.y);
    }

    float bb[8];
#pragma unroll
    for (int c = 0; c < 8; c++) bb[c] = bias ? bias[c0 + c] : 0.f;

#pragma unroll
    for (int r = 0; r < 4; r++) {
        const int rgl = row0 + r0 + r;
        if (rgl >= nrows) continue;
        float y[8];
#pragma unroll
        for (int cp = 0; cp < 4; cp++) {
            const float2 f = unpack2(acc[r][cp]);
            y[2 * cp]     = f.x + bb[2 * cp];
            y[2 * cp + 1] = f.y + bb[2 * cp + 1];
        }
        float4* op = (float4*)(out + (size_t)rgl * O + c0);
        op[0] = make_float4(y[0], y[1], y[2], y[3]);
        op[1] = make_float4(y[4], y[5], y[6], y[7]);
    }
}

// ================= x -> fp16 mirror =================
__global__ void x2h_kernel() {
    const int idx = blockIdx.x * blockDim.x + threadIdx.x;
    if (idx >= NN * (AA / 2)) return;
    const float2 xv = *((const float2*)(g_x + (size_t)2 * idx));
    ((unsigned*)g_xh)[idx] = h2_to_u(__floats2half2_rn(xv.x, xv.y));
}

// ================= conv GEMM via HMMA: c,d = xh @ Wc, xh @ Wd ==================
// 128 threads (4 warps); block = 64 atoms; A fragments read from global xh.
// Same fragment/epilogue pattern as gatedmma (validated), K=64.
__global__ void __launch_bounds__(128, 4)
convmma_kernel(const __half* __restrict__ xh, const uint2* __restrict__ wcdf,
               __half* __restrict__ outc, __half* __restrict__ outd)
{
    __shared__ __align__(16) uint2  sB[4 * 16 * 32];     // 16KB one W part
    __shared__ __align__(16) __half sy[64 * 136];        // 17KB output staging

    const int t    = threadIdx.x;
    const int w    = t >> 5;
    const int lane = t & 31;
    const int g    = lane >> 2;
    const int i    = lane & 3;
    const int row0 = blockIdx.x * 64;

    const unsigned* Ag = (const unsigned*)xh;
    const unsigned arow0 = (unsigned)(row0 + w * 16 + g) * 32;   // u32 pitch 32 (K=64 halves)
    const unsigned arow1 = arow0 + 8 * 32;

    for (int s = 0; s < 2; s++) {
        for (int idx = t; idx < 4 * 16 * 32; idx += 128) sB[idx] = wcdf[s * 2048 + idx];
        __syncthreads();

        float acc[16][4];
#pragma unroll
        for (int nt = 0; nt < 16; nt++)
#pragma unroll
            for (int c = 0; c < 4; c++) acc[nt][c] = 0.f;

#pragma unroll
        for (int ks = 0; ks < 4; ks++) {
            const unsigned a0 = Ag[arow0 + ks * 8 + i];
            const unsigned a1 = Ag[arow1 + ks * 8 + i];
            const unsigned a2 = Ag[arow0 + ks * 8 + i + 4];
            const unsigned a3 = Ag[arow1 + ks * 8 + i + 4];
#pragma unroll
            for (int nt = 0; nt < 16; nt++) {
                const uint2 b = sB[(ks * 16 + nt) * 32 + lane];
                mma16816(acc[nt][0], acc[nt][1], acc[nt][2], acc[nt][3],
                         a0, a1, a2, a3, b.x, b.y);
            }
        }

        const int r0 = w * 16 + g, r1 = r0 + 8;
#pragma unroll
        for (int nt = 0; nt < 16; nt++) {
            *((unsigned*)(sy + r0 * 136 + nt * 8 + i * 2)) =
                h2_to_u(__floats2half2_rn(acc[nt][0], acc[nt][1]));
            *((unsigned*)(sy + r1 * 136 + nt * 8 + i * 2)) =
                h2_to_u(__floats2half2_rn(acc[nt][2], acc[nt][3]));
        }
        __syncthreads();

        __half* outp = s ? outd : outc;
        for (int idx = t; idx < 64 * 16; idx += 128) {
            const int r = idx >> 4, ui = idx & 15;
            const uint4 vv = *((const uint4*)(sy + r * 136 + ui * 8));
            *((uint4*)(outp + (size_t)(row0 + r) * A2 + ui * 8)) = vv;
        }
        __syncthreads();
    }
}

// ---------------- zero BN stats ----------------
__global__ void zero_stats_kernel() {
    const int t = threadIdx.x;
    if (t < A2) { g_s1[t] = 0.0; g_q1[t] = 0.0; }
    if (t < AA) { g_s2[t] = 0.0; g_q2[t] = 0.0; }
}

// ================= gated via HMMA: y[e,128] = nfe[e,:]@W3 + c[n]+d[idx]+b ======
// 128 threads (4 warps); 192 edges/block in 3 passes of 64; warp = 16-edge strip.
__global__ void __launch_bounds__(128, 4)
gatedmma_kernel(const int* __restrict__ nbr_idx,
                const uint2* __restrict__ w3f, const float* __restrict__ bias)
{
    __shared__ __align__(16) uint2  sB[3 * 16 * 32];     // 12KB  B fragments
    __shared__ __align__(16) __half scd[64 * 136];       // 17KB  cd / y buffer (pad 8)

    const int t    = threadIdx.x;
    const int w    = t >> 5;
    const int lane = t & 31;
    const int g    = lane >> 2;
    const int i    = lane & 3;

    for (int idx = t; idx < 3 * 16 * 32; idx += 128) sB[idx] = w3f[idx];
    const float4 bias4 = *((const float4*)(bias + lane * 4));

    float s_acc = 0.f, q_acc = 0.f;
    const unsigned eblock = blockIdx.x * 192;
    __syncthreads();

    for (int pass = 0; pass < 3; pass++) {
        const unsigned e0 = eblock + pass * 64;

        // ---- stage cd = c[n] + d[idx] + bias into scd (warp w: edges w*16..+15)
        for (int k = 0; k < 16; k++) {
            const unsigned e = e0 + w * 16 + k;
            const unsigned n = e / MM;
            const int j = nbr_idx[e];
            const uint2 cu = ((const uint2*)g_ch)[(size_t)n * 32 + lane];
            const uint2 du = ((const uint2*)g_dh)[(size_t)j * 32 + lane];
            const float2 ca = u_to_f2(cu.x), cb2 = u_to_f2(cu.y);
            const float2 da = u_to_f2(du.x), db2 = u_to_f2(du.y);
            const float v0 = ca.x + da.x + bias4.x;
            const float v1 = ca.y + da.y + bias4.y;
            const float v2 = cb2.x + db2.x + bias4.z;
            const float v3 = cb2.y + db2.y + bias4.w;
            unsigned* dst = (unsigned*)(scd + (w * 16 + k) * 136 + lane * 4);
            dst[0] = h2_to_u(__floats2half2_rn(v0, v1));
            dst[1] = h2_to_u(__floats2half2_rn(v2, v3));
        }
        __syncthreads();

        // ---- mma: warp strip of 16 edges x 128 cols
        float acc[16][4];
#pragma unroll
        for (int nt = 0; nt < 16; nt++)
#pragma unroll
            for (int c = 0; c < 4; c++) acc[nt][c] = 0.f;

        const unsigned* Ag = (const unsigned*)g_nfe;
        const unsigned arow0 = (e0 + w * 16 + g) * (KP / 2);
        const unsigned arow1 = arow0 + 8 * (KP / 2);

#pragma unroll
        for (int ks = 0; ks < 3; ks++) {
            const unsigned a0 = Ag[arow0 + ks * 8 + i];
            const unsigned a1 = Ag[arow1 + ks * 8 + i];
            const unsigned a2 = Ag[arow0 + ks * 8 + i + 4];
            const unsigned a3 = Ag[arow1 + ks * 8 + i + 4];
#pragma unroll
            for (int nt = 0; nt < 16; nt++) {
                const uint2 b = sB[(ks * 16 + nt) * 32 + lane];
                mma16816(acc[nt][0], acc[nt][1], acc[nt][2], acc[nt][3],
                         a0, a1, a2, a3, b.x, b.y);
            }
        }

        // ---- y = acc + cd, write back into scd (same slots this thread owns)
        const int r0 = w * 16 + g, r1 = r0 + 8;
#pragma unroll
        for (int nt = 0; nt < 16; nt++) {
            unsigned* p0 = (unsigned*)(scd + r0 * 136 + nt * 8 + i * 2);
            unsigned* p1 = (unsigned*)(scd + r1 * 136 + nt * 8 + i * 2);
            const float2 cd0 = u_to_f2(*p0);
            const float2 cd1 = u_to_f2(*p1);
            *p0 = h2_to_u(__floats2half2_rn(acc[nt][0] + cd0.x, acc[nt][1] + cd0.y));
            *p1 = h2_to_u(__floats2half2_rn(acc[nt][2] + cd1.x, acc[nt][3] + cd1.y));
        }
        __syncthreads();

        // ---- stats (thread t = column t) + coalesced store to g_gatedh
        for (int r = 0; r < 64; r++) {
            const float v = __half2float(scd[r * 136 + t]);
            s_acc += v; q_acc += v * v;
        }
        for (int idx = t; idx < 64 * 16; idx += 128) {
            const int r = idx >> 4, ui = idx & 15;
            const uint4 vv = *((const uint4*)(scd + r * 136 + ui * 8));
            *((uint4*)(g_gatedh + (size_t)(e0 + r) * A2 + ui * 8)) = vv;
        }
        __syncthreads();
    }

    atomicAdd(&g_s1[t], (double)s_acc);
    atomicAdd(&g_q1[t], (double)q_acc);
}

__global__ void finalize1_kernel(const float* __restrict__ g1, const float* __restrict__ b1) {
    const int o = threadIdx.x;
    const double cnt = (double)NN * MM;
    const double mean = g_s1[o] / cnt;
    const double var  = g_q1[o] / cnt - mean * mean;
    const float scale = g1[o] * rsqrtf((float)var + EPSL);
    g_scale1[o] = scale;
    g_shift1[o] = b1[o] - (float)mean * scale;
}

// ---------------- gatesum (edge-major layout) ----------------
__global__ void gatesum_kernel() {
    __shared__ float ss[16][64], sq[16][64];
    const int t = threadIdx.x;
    const int slot = t >> 4;
    const int col0 = 4 * (t & 15);

    const float4 scf = *((const float4*)(g_scale1 + col0));
    const float4 shf = *((const float4*)(g_shift1 + col0));
    const float4 scc = *((const float4*)(g_scale1 + 64 + col0));
    const float4 shc = *((const float4*)(g_shift1 + 64 + col0));
    const float scfv[4] = {scf.x, scf.y, scf.z, scf.w};
    const float shfv[4] = {shf.x, shf.y, shf.z, shf.w};
    const float sccv[4] = {scc.x, scc.y, scc.z, scc.w};
    const float shcv[4] = {shc.x, shc.y, shc.z, shc.w};

    float sc[4] = {0.f, 0.f, 0.f, 0.f}, qc[4] = {0.f, 0.f, 0.f, 0.f};

    for (int i2 = 0; i2 < 4; i2++) {
        const int n = blockIdx.x * 64 + slot * 4 + i2;
        if (n >= NN) break;
        float acc[4] = {0.f, 0.f, 0.f, 0.f};
#pragma unroll
        for (int m = 0; m < MM; m++) {
            const __half* ge = g_gatedh + (size_t)(n * MM + m) * A2;
            const uint2 uf = *((const uint2*)(ge + col0));
            const uint2 uc = *((const uint2*)(ge + 64 + col0));
            const float2 f0 = u_to_f2(uf.x), f1 = u_to_f2(uf.y);
            const float2 c0 = u_to_f2(uc.x), c1 = u_to_f2(uc.y);
            acc[0] += sg_f(f0.x * scfv[0] + shfv[0]) * sp_f(c0.x * sccv[0] + shcv[0]);
            acc[1] += sg_f(f0.y * scfv[1] + shfv[1]) * sp_f(c0.y * sccv[1] + shcv[1]);
            acc[2] += sg_f(f1.x * scfv[2] + shfv[2]) * sp_f(c1.x * sccv[2] + shcv[2]);
            acc[3] += sg_f(f1.y * scfv[3] + shfv[3]) * sp_f(c1.y * sccv[3] + shcv[3]);
        }
        *((float4*)(g_ns + (size_t)n * AA + col0)) = make_float4(acc[0], acc[1], acc[2], acc[3]);
#pragma unroll
        for (int c = 0; c < 4; c++) { sc[c] += acc[c]; qc[c] += acc[c] * acc[c]; }
    }

#pragma unroll
    for (int c = 0; c < 4; c++) { ss[slot][col0 + c] = sc[c]; sq[slot][col0 + c] = qc[c]; }
    __syncthreads();
    if (t < 64) {
        float a = 0.f, b = 0.f;
#pragma unroll
        for (int s = 0; s < 16; s++) { a += ss[s][t]; b += sq[s][t]; }
        atomicAdd(&g_s2[t], (double)a);
        atomicAdd(&g_q2[t], (double)b);
    }
}

__global__ void finalize2_kernel(const float* __restrict__ g2, const float* __restrict__ b2) {
    const int a = threadIdx.x;
    const double cnt = (double)NN;
    const double mean = g_s2[a] / cnt;
    const double var  = g_q2[a] / cnt - mean * mean;
    const float scale = g2[a] * rsqrtf((float)var + EPSL);
    g_scale2[a] = scale;
    g_shift2[a] = b2[a] - (float)mean * scale;
}

// ---------------- update: x = softplus(x + ns*sc2 + sh2); refresh xh -----------
__global__ void update_kernel() {
    const int idx = blockIdx.x * blockDim.x + threadIdx.x;
    if (idx >= NN * (AA / 2)) return;
    const int a0 = (2 * idx) & 63;
    const float2 xv = *((const float2*)(g_x + (size_t)2 * idx));
    const float2 nv = *((const float2*)(g_ns + (size_t)2 * idx));
    const float v0 = sp_f(xv.x + nv.x * g_scale2[a0]     + g_shift2[a0]);
    const float v1 = sp_f(xv.y + nv.y * g_scale2[a0 + 1] + g_shift2[a0 + 1]);
    *((float2*)(g_x + (size_t)2 * idx)) = make_float2(v0, v1);
    ((unsigned*)g_xh)[idx] = h2_to_u(__floats2half2_rn(v0, v1));
}

// ---------------- fused pool + head ----------------
__global__ void head2_kernel(const float* __restrict__ fc_W, const float* __restrict__ fc_b,
                             const float* __restrict__ out_W, const float* __restrict__ out_b,
                             float* __restrict__ out)
{
    __shared__ float sred[2][64];
    __shared__ float spm[64];
    __shared__ float red[128];
    const int c = blockIdx.x, t = threadIdx.x;
    const int a = t & 63, half = t >> 6;

    float s = 0.f;
    const int r0 = c * 100 + half * 50;
    for (int i = 0; i < 50; i++) s += g_x[(r0 + i) * 64 + a];
    sred[half][a] = s;
    __syncthreads();
    if (t < 64) spm[t] = sp_f((sred[0][t] + sred[1][t]) * 0.01f);
    __syncthreads();

    float h = fc_b[t];
#pragma unroll
    for (int aa = 0; aa < 64; aa++) h += spm[aa] * fc_W[aa * HH + t];
    red[t] = sp_f(h) * out_W[t];
    __syncthreads();
    for (int sft = 64; sft > 0; sft >>= 1) {
        if (t < sft) red[t] += red[t + sft];
        __syncthreads();
    }
    if (t == 0) out[c] = red[0] + out_b[0];
}

// ---------------- host orchestration ----------------
extern "C" void kernel_launch(void* const* d_in, const int* in_sizes, int n_in,
                              void* d_out, int out_size)
{
    const float* atom_fea = (const float*)d_in[0];
    const float* nbr_fea  = (const float*)d_in[1];
    const int*   nbr_idx  = (const int*)  d_in[2];
    const float* emb_W    = (const float*)d_in[4];
    const float* emb_b    = (const float*)d_in[5];
    const float* conv_W   = (const float*)d_in[6];
    const float* conv_b   = (const float*)d_in[7];
    const float* bn1_g    = (const float*)d_in[8];
    const float* bn1_b    = (const float*)d_in[9];
    const float* bn2_g    = (const float*)d_in[10];
    const float* bn2_b    = (const float*)d_in[11];
    const float* fc_W     = (const float*)d_in[12];
    const float* fc_b     = (const float*)d_in[13];
    const float* out_W    = (const float*)d_in[14];
    const float* out_b    = (const float*)d_in[15];
    float* out = (float*)d_out;

    float *px;
    __half *pxh, *pc, *pd;
    uint2 *pw3f, *pwcdf;
    cudaGetSymbolAddress((void**)&px,    g_x);
    cudaGetSymbolAddress((void**)&pxh,   g_xh);
    cudaGetSymbolAddress((void**)&pc,    g_ch);
    cudaGetSymbolAddress((void**)&pd,    g_dh);
    cudaGetSymbolAddress((void**)&pw3f,  g_w3f);
    cudaGetSymbolAddress((void**)&pwcdf, g_wcdf);

    const int gemmBlocks = NNP / 64;   // 1563
    const size_t smemE = (size_t)ORIGF * 64 * 4 + (size_t)ORIGF * AA * 4;  // 46KB

    nfe_prep<<<(NE * (KP / 2) + 255) / 256, 256>>>(nbr_fea);
    w3f_prep<<<(NCONVL * 3 * 16 * 32 + 255) / 256, 256>>>(conv_W);
    wcd_prep<<<(NCONVL * 2 * 4 * 16 * 32 + 255) / 256, 256>>>(conv_W);
    gemmT_kernel<ORIGF, AA><<<gemmBlocks, 128, smemE>>>(atom_fea, emb_W, emb_b, px, NN);
    x2h_kernel<<<(NN * 32 + 255) / 256, 256>>>();

    for (int i = 0; i < NCONVL; i++) {
        zero_stats_kernel<<<1, 128>>>();
        if (i > 0) update_kernel<<<(NN * 32 + 255) / 256, 256>>>();
        convmma_kernel<<<gemmBlocks, 128>>>(pxh, pwcdf + (size_t)i * 4096, pc, pd);
        gatedmma_kernel<<<NE / 192, 128>>>(nbr_idx, pw3f + (size_t)i * 1536,
                                           conv_b + i * A2);
        finalize1_kernel<<<1, A2>>>(bn1_g + i * A2, bn1_b + i * A2);
        gatesum_kernel<<<(NN + 63) / 64, 256>>>();
        finalize2_kernel<<<1, AA>>>(bn2_g + i * AA, bn2_b + i * AA);
    }

    update_kernel<<<(NN * 32 + 255) / 256, 256>>>();
    head2_kernel<<<NC0, 128>>>(fc_W, fc_b, out_W, out_b, out);
}